// round 3
// baseline (speedup 1.0000x reference)
#include <cuda_runtime.h>
#include <cuda_bf16.h>
#include <cstdint>

// Problem constants
#define BB 8
#define NN 4096
#define CC 128
#define SS 1024          // NPOINT
#define KK 64            // NSAMPLE
#define CIN 131          // 3 + C
#define R2 0.04f
#define ROWS (BB*SS*KK)  // 524288
#define INV_ROWS (1.0f/524288.0f)
#define EPSV 1e-5f

// ------------------------- scratch (device globals) -------------------------
__device__ float g_featT[BB*NN*CC];            // (B,N,C) transposed features
__device__ float g_newxyz[BB*SS*3];
__device__ int   g_gi[BB*SS*KK];
__device__ float g_y1[(size_t)ROWS*128];
__device__ float g_y2[(size_t)ROWS*128];
__device__ float g_y3[(size_t)ROWS*256];
// per-block partial sums (deterministic BN stats)
__device__ float g_p1a[8192*128], g_p2a[8192*128];
__device__ float g_p1b[8192*128], g_p2b[8192*128];
__device__ float g_p1c[8192*256], g_p2c[8192*256];
// reduced stats
__device__ float g_s1a[128], g_s2a[128];
__device__ float g_s1b[128], g_s2b[128];
__device__ float g_s1c[256], g_s2c[256];

// ------------------------- feature transpose (B,C,N)->(B,N,C) ---------------
__global__ void transpose_feat(const float* __restrict__ f) {
    __shared__ float t[32][33];
    int b = blockIdx.z;
    int n0 = blockIdx.x * 32;
    int c0 = blockIdx.y * 32;
    int tx = threadIdx.x, ty = threadIdx.y;
#pragma unroll
    for (int k = 0; k < 4; k++) {
        int c = c0 + ty + k * 8;
        t[ty + k * 8][tx] = f[(size_t)b * CC * NN + (size_t)c * NN + n0 + tx];
    }
    __syncthreads();
#pragma unroll
    for (int k = 0; k < 4; k++) {
        int n = n0 + ty + k * 8;
        g_featT[((size_t)b * NN + n) * CC + c0 + tx] = t[tx][ty + k * 8];
    }
}

// ------------------------- FPS ----------------------------------------------
// grid = B, block = 512. Each thread owns 8 points (coords+dist in registers).
__global__ __launch_bounds__(512) void fps_kernel(const float* __restrict__ xyz,
                                                  float* __restrict__ out_newxyz) {
    int b = blockIdx.x;
    int tid = threadIdx.x;
    __shared__ float cent[3];
    __shared__ float red_d[16];
    __shared__ int   red_i[16];
    __shared__ int   sFar;

    float px[8], py[8], pz[8], dist[8];
#pragma unroll
    for (int j = 0; j < 8; j++) {
        int p = tid + j * 512;
        const float* P = xyz + ((size_t)b * NN + p) * 3;
        px[j] = P[0]; py[j] = P[1]; pz[j] = P[2];
        dist[j] = 1e10f;
    }

    int far = 0;
    int lane = tid & 31;
    int warp = tid >> 5;

    for (int it = 0; it < SS; it++) {
        // owner of current farthest publishes centroid + outputs
        if (tid == (far & 511)) {
            int j = far >> 9;
            cent[0] = px[j]; cent[1] = py[j]; cent[2] = pz[j];
            size_t o = ((size_t)b * SS + it) * 3;
            out_newxyz[o]     = px[j];  g_newxyz[o]     = px[j];
            out_newxyz[o + 1] = py[j];  g_newxyz[o + 1] = py[j];
            out_newxyz[o + 2] = pz[j];  g_newxyz[o + 2] = pz[j];
        }
        __syncthreads();
        float cx = cent[0], cy = cent[1], cz = cent[2];

        float bd = -1.0f; int bi = 0x7fffffff;
#pragma unroll
        for (int j = 0; j < 8; j++) {
            // strict (no-FMA) arithmetic to match reference bit pattern
            float dx = __fsub_rn(px[j], cx);
            float dy = __fsub_rn(py[j], cy);
            float dz = __fsub_rn(pz[j], cz);
            float d = __fadd_rn(__fadd_rn(__fmul_rn(dx, dx), __fmul_rn(dy, dy)),
                                __fmul_rn(dz, dz));
            dist[j] = fminf(dist[j], d);
            int p = tid + j * 512;
            if (dist[j] > bd || (dist[j] == bd && p < bi)) { bd = dist[j]; bi = p; }
        }
        // warp reduce (max, tie -> min index)
#pragma unroll
        for (int off = 16; off > 0; off >>= 1) {
            float od = __shfl_down_sync(0xffffffffu, bd, off);
            int   oi = __shfl_down_sync(0xffffffffu, bi, off);
            if (od > bd || (od == bd && oi < bi)) { bd = od; bi = oi; }
        }
        if (lane == 0) { red_d[warp] = bd; red_i[warp] = bi; }
        __syncthreads();
        if (warp == 0) {
            float vd = (lane < 16) ? red_d[lane] : -1.0f;
            int   vi = (lane < 16) ? red_i[lane] : 0x7fffffff;
#pragma unroll
            for (int off = 8; off > 0; off >>= 1) {
                float od = __shfl_down_sync(0xffffffffu, vd, off);
                int   oi = __shfl_down_sync(0xffffffffu, vi, off);
                if (od > vd || (od == vd && oi < vi)) { vd = od; vi = oi; }
            }
            if (lane == 0) sFar = vi;
        }
        __syncthreads();
        far = sFar;
    }
}

// ------------------------- query_ball ---------------------------------------
// warp per query; first-64-by-index within radius; pad with first.
__global__ __launch_bounds__(256) void qball_kernel(const float* __restrict__ xyz) {
    int q = blockIdx.x * 8 + (threadIdx.x >> 5);
    int lane = threadIdx.x & 31;
    int b = q >> 10;
    float qx = g_newxyz[q * 3], qy = g_newxyz[q * 3 + 1], qz = g_newxyz[q * 3 + 2];
    int* out = g_gi + (size_t)q * KK;
    int cnt = 0;
    for (int base = 0; base < NN && cnt < KK; base += 32) {
        int p = base + lane;
        const float* P = xyz + ((size_t)b * NN + p) * 3;
        float dx = P[0] - qx, dy = P[1] - qy, dz = P[2] - qz;
        float d = dx * dx + dy * dy + dz * dz;
        bool in = (d <= R2);
        unsigned m = __ballot_sync(0xffffffffu, in);
        if (in) {
            int slot = cnt + __popc(m & ((1u << lane) - 1u));
            if (slot < KK) out[slot] = p;
        }
        cnt += __popc(m);
    }
    __syncwarp();
    int total = cnt < KK ? cnt : KK;
    int f0 = out[0];
    for (int slot = total + lane; slot < KK; slot += 32) out[slot] = f0;
}

// ------------------------- GEMM1 (fused gather + concat) --------------------
// block per (b,s): 64 rows x 131 -> 128. Deterministic per-block BN partials.
#define SM1_FLOATS (64*132 + 131*128)
__global__ __launch_bounds__(256, 2) void gemm1_kernel(const float* __restrict__ xyz,
                                                       const float* __restrict__ W1) {
    extern __shared__ float sm[];
    float* xs = sm;              // [64][132]
    float* ws = sm + 64 * 132;   // [131][128]
    __shared__ int sidx[64];
    __shared__ float pr[8][128];

    int bs = blockIdx.x;
    int b = bs >> 10;
    int tid = threadIdx.x;

    if (tid < 64) sidx[tid] = g_gi[(size_t)bs * KK + tid];
    for (int e = tid; e < CIN * 128; e += 256) ws[e] = W1[e];
    __syncthreads();

    float qx = g_newxyz[bs * 3], qy = g_newxyz[bs * 3 + 1], qz = g_newxyz[bs * 3 + 2];
    if (tid < 64) {
        int p = sidx[tid];
        const float* P = xyz + ((size_t)b * NN + p) * 3;
        xs[tid * 132 + 0] = P[0] - qx;
        xs[tid * 132 + 1] = P[1] - qy;
        xs[tid * 132 + 2] = P[2] - qz;
    }
    for (int e = tid; e < 64 * 128; e += 256) {
        int r = e >> 7, c = e & 127;
        xs[r * 132 + 3 + c] = g_featT[((size_t)b * NN + sidx[r]) * CC + c];
    }
    __syncthreads();

    int tx = tid & 31, ty = tid >> 5;
    float acc[8][4];
#pragma unroll
    for (int r = 0; r < 8; r++) { acc[r][0] = acc[r][1] = acc[r][2] = acc[r][3] = 0.f; }

    for (int kk = 0; kk < CIN; kk++) {
        float4 w = *(const float4*)&ws[kk * 128 + tx * 4];
#pragma unroll
        for (int r = 0; r < 8; r++) {
            float xv = xs[(ty * 8 + r) * 132 + kk];
            acc[r][0] += xv * w.x; acc[r][1] += xv * w.y;
            acc[r][2] += xv * w.z; acc[r][3] += xv * w.w;
        }
    }

    float s1[4] = {0, 0, 0, 0}, s2[4] = {0, 0, 0, 0};
    float* yo = g_y1 + ((size_t)bs * 64) * 128;
#pragma unroll
    for (int r = 0; r < 8; r++) {
        *(float4*)&yo[(ty * 8 + r) * 128 + tx * 4] =
            make_float4(acc[r][0], acc[r][1], acc[r][2], acc[r][3]);
#pragma unroll
        for (int c = 0; c < 4; c++) { s1[c] += acc[r][c]; s2[c] += acc[r][c] * acc[r][c]; }
    }
#pragma unroll
    for (int c = 0; c < 4; c++) pr[ty][tx * 4 + c] = s1[c];
    __syncthreads();
    if (tid < 128) {
        float t = 0;
#pragma unroll
        for (int y = 0; y < 8; y++) t += pr[y][tid];
        g_p1a[(size_t)bs * 128 + tid] = t;
    }
    __syncthreads();
#pragma unroll
    for (int c = 0; c < 4; c++) pr[ty][tx * 4 + c] = s2[c];
    __syncthreads();
    if (tid < 128) {
        float t = 0;
#pragma unroll
        for (int y = 0; y < 8; y++) t += pr[y][tid];
        g_p2a[(size_t)bs * 128 + tid] = t;
    }
}

// ------------------------- stats reduce (fixed order, deterministic) --------
// One block per channel; 256-thread fixed-shape tree over 8192 partial rows.
// NOTE: device globals are referenced from DEVICE code only (passing a
// __device__ symbol as a host-side kernel arg yields the host shadow address
// — that was the Round-1 bug that zeroed all BN stats).
__device__ __forceinline__ void reduce_impl(const float* __restrict__ p1,
                                            const float* __restrict__ p2,
                                            float* __restrict__ s1,
                                            float* __restrict__ s2,
                                            int nrows, int nch) {
    int ch = blockIdx.x;
    int tid = threadIdx.x;
    float a = 0.f, b = 0.f;
    for (int t = tid; t < nrows; t += 256) {
        a += p1[(size_t)t * nch + ch];
        b += p2[(size_t)t * nch + ch];
    }
    __shared__ float sa[256], sb[256];
    sa[tid] = a; sb[tid] = b;
    __syncthreads();
#pragma unroll
    for (int off = 128; off > 0; off >>= 1) {
        if (tid < off) { sa[tid] += sa[tid + off]; sb[tid] += sb[tid + off]; }
        __syncthreads();
    }
    if (tid == 0) { s1[ch] = sa[0]; s2[ch] = sb[0]; }
}
__global__ __launch_bounds__(256) void reduce_a() { reduce_impl(g_p1a, g_p2a, g_s1a, g_s2a, 8192, 128); }
__global__ __launch_bounds__(256) void reduce_b() { reduce_impl(g_p1b, g_p2b, g_s1b, g_s2b, 8192, 128); }
__global__ __launch_bounds__(256) void reduce_c() { reduce_impl(g_p1c, g_p2c, g_s1c, g_s2c, 8192, 256); }

// ------------------------- GEMM2 (norm+relu fused on load) ------------------
#define SM2_FLOATS (64*128 + 128*128)
__global__ __launch_bounds__(256, 2) void gemm2_kernel(const float* __restrict__ W2,
                                                       const float* __restrict__ gv,
                                                       const float* __restrict__ bv) {
    extern __shared__ float sm[];
    float* xs = sm;             // [64][128]
    float* ws = sm + 64 * 128;  // [128][128]
    __shared__ float na[128], nb[128];
    __shared__ float pr[8][128];

    int tile = blockIdx.x;
    int tid = threadIdx.x;
    if (tid < 128) {
        float m = g_s1a[tid] * INV_ROWS;
        float v = g_s2a[tid] * INV_ROWS - m * m;
        float a = rsqrtf(v + EPSV) * gv[tid];
        na[tid] = a; nb[tid] = bv[tid] - m * a;
    }
    for (int e = tid; e < 128 * 128; e += 256) ws[e] = W2[e];
    __syncthreads();

    const float* yi = g_y1 + (size_t)tile * 64 * 128;
    for (int e = tid; e < 64 * 128; e += 256) {
        int c = e & 127;
        xs[e] = fmaxf(fmaf(yi[e], na[c], nb[c]), 0.f);
    }
    __syncthreads();

    int tx = tid & 31, ty = tid >> 5;
    float acc[8][4];
#pragma unroll
    for (int r = 0; r < 8; r++) { acc[r][0] = acc[r][1] = acc[r][2] = acc[r][3] = 0.f; }
    for (int kk = 0; kk < 128; kk++) {
        float4 w = *(const float4*)&ws[kk * 128 + tx * 4];
#pragma unroll
        for (int r = 0; r < 8; r++) {
            float xv = xs[(ty * 8 + r) * 128 + kk];
            acc[r][0] += xv * w.x; acc[r][1] += xv * w.y;
            acc[r][2] += xv * w.z; acc[r][3] += xv * w.w;
        }
    }

    float s1[4] = {0, 0, 0, 0}, s2[4] = {0, 0, 0, 0};
    float* yo = g_y2 + (size_t)tile * 64 * 128;
#pragma unroll
    for (int r = 0; r < 8; r++) {
        *(float4*)&yo[(ty * 8 + r) * 128 + tx * 4] =
            make_float4(acc[r][0], acc[r][1], acc[r][2], acc[r][3]);
#pragma unroll
        for (int c = 0; c < 4; c++) { s1[c] += acc[r][c]; s2[c] += acc[r][c] * acc[r][c]; }
    }
#pragma unroll
    for (int c = 0; c < 4; c++) pr[ty][tx * 4 + c] = s1[c];
    __syncthreads();
    if (tid < 128) {
        float t = 0;
#pragma unroll
        for (int y = 0; y < 8; y++) t += pr[y][tid];
        g_p1b[(size_t)tile * 128 + tid] = t;
    }
    __syncthreads();
#pragma unroll
    for (int c = 0; c < 4; c++) pr[ty][tx * 4 + c] = s2[c];
    __syncthreads();
    if (tid < 128) {
        float t = 0;
#pragma unroll
        for (int y = 0; y < 8; y++) t += pr[y][tid];
        g_p2b[(size_t)tile * 128 + tid] = t;
    }
}

// ------------------------- GEMM3 (128 -> 256, two N-halves) -----------------
__global__ __launch_bounds__(256, 2) void gemm3_kernel(const float* __restrict__ W3,
                                                       const float* __restrict__ gv,
                                                       const float* __restrict__ bv) {
    extern __shared__ float sm[];
    float* xs = sm;
    float* ws = sm + 64 * 128;
    __shared__ float na[128], nb[128];
    __shared__ float pr[8][128];

    int tile = blockIdx.x >> 1;
    int half = blockIdx.x & 1;
    int tid = threadIdx.x;
    if (tid < 128) {
        float m = g_s1b[tid] * INV_ROWS;
        float v = g_s2b[tid] * INV_ROWS - m * m;
        float a = rsqrtf(v + EPSV) * gv[tid];
        na[tid] = a; nb[tid] = bv[tid] - m * a;
    }
    for (int e = tid; e < 128 * 128; e += 256) {
        int kk = e >> 7, j = e & 127;
        ws[e] = W3[kk * 256 + half * 128 + j];
    }
    __syncthreads();

    const float* yi = g_y2 + (size_t)tile * 64 * 128;
    for (int e = tid; e < 64 * 128; e += 256) {
        int c = e & 127;
        xs[e] = fmaxf(fmaf(yi[e], na[c], nb[c]), 0.f);
    }
    __syncthreads();

    int tx = tid & 31, ty = tid >> 5;
    float acc[8][4];
#pragma unroll
    for (int r = 0; r < 8; r++) { acc[r][0] = acc[r][1] = acc[r][2] = acc[r][3] = 0.f; }
    for (int kk = 0; kk < 128; kk++) {
        float4 w = *(const float4*)&ws[kk * 128 + tx * 4];
#pragma unroll
        for (int r = 0; r < 8; r++) {
            float xv = xs[(ty * 8 + r) * 128 + kk];
            acc[r][0] += xv * w.x; acc[r][1] += xv * w.y;
            acc[r][2] += xv * w.z; acc[r][3] += xv * w.w;
        }
    }

    float s1[4] = {0, 0, 0, 0}, s2[4] = {0, 0, 0, 0};
    float* yo = g_y3 + (size_t)tile * 64 * 256 + half * 128;
#pragma unroll
    for (int r = 0; r < 8; r++) {
        *(float4*)&yo[(ty * 8 + r) * 256 + tx * 4] =
            make_float4(acc[r][0], acc[r][1], acc[r][2], acc[r][3]);
#pragma unroll
        for (int c = 0; c < 4; c++) { s1[c] += acc[r][c]; s2[c] += acc[r][c] * acc[r][c]; }
    }
#pragma unroll
    for (int c = 0; c < 4; c++) pr[ty][tx * 4 + c] = s1[c];
    __syncthreads();
    if (tid < 128) {
        float t = 0;
#pragma unroll
        for (int y = 0; y < 8; y++) t += pr[y][tid];
        g_p1c[(size_t)tile * 256 + half * 128 + tid] = t;
    }
    __syncthreads();
#pragma unroll
    for (int c = 0; c < 4; c++) pr[ty][tx * 4 + c] = s2[c];
    __syncthreads();
    if (tid < 128) {
        float t = 0;
#pragma unroll
        for (int y = 0; y < 8; y++) t += pr[y][tid];
        g_p2c[(size_t)tile * 256 + half * 128 + tid] = t;
    }
}

// ------------------------- final: norm + relu + max over K + transpose ------
__global__ __launch_bounds__(256) void final_kernel(const float* __restrict__ gv,
                                                    const float* __restrict__ bv,
                                                    float* __restrict__ out) {
    int bs = blockIdx.x;
    int c = threadIdx.x;
    float m = g_s1c[c] * INV_ROWS;
    float v = g_s2c[c] * INV_ROWS - m * m;
    float a = rsqrtf(v + EPSV) * gv[c];
    float bb = bv[c] - m * a;
    const float* Y = g_y3 + (size_t)bs * 64 * 256;
    float mx = -1e30f;
#pragma unroll 8
    for (int k = 0; k < 64; k++) mx = fmaxf(mx, fmaf(Y[(size_t)k * 256 + c], a, bb));
    float r = fmaxf(mx, 0.f);
    int b = bs >> 10, s = bs & 1023;
    out[(size_t)b * 256 * 1024 + (size_t)c * 1024 + s] = r;
}

// ------------------------- launch -------------------------------------------
extern "C" void kernel_launch(void* const* d_in, const int* in_sizes, int n_in,
                              void* d_out, int out_size) {
    const float* xyz  = (const float*)d_in[0];
    const float* feat = (const float*)d_in[1];
    const float* W1 = (const float*)d_in[2];
    const float* g1 = (const float*)d_in[3];
    const float* b1 = (const float*)d_in[4];
    const float* W2 = (const float*)d_in[5];
    const float* g2 = (const float*)d_in[6];
    const float* b2 = (const float*)d_in[7];
    const float* W3 = (const float*)d_in[8];
    const float* g3 = (const float*)d_in[9];
    const float* b3 = (const float*)d_in[10];
    float* out = (float*)d_out;

    int sm1 = SM1_FLOATS * 4;
    int sm2 = SM2_FLOATS * 4;
    cudaFuncSetAttribute(gemm1_kernel, cudaFuncAttributeMaxDynamicSharedMemorySize, sm1);
    cudaFuncSetAttribute(gemm2_kernel, cudaFuncAttributeMaxDynamicSharedMemorySize, sm2);
    cudaFuncSetAttribute(gemm3_kernel, cudaFuncAttributeMaxDynamicSharedMemorySize, sm2);

    transpose_feat<<<dim3(NN / 32, CC / 32, BB), dim3(32, 8)>>>(feat);
    fps_kernel<<<BB, 512>>>(xyz, out);                 // writes new_xyz to d_out[0:24576]
    qball_kernel<<<1024, 256>>>(xyz);
    gemm1_kernel<<<8192, 256, sm1>>>(xyz, W1);
    reduce_a<<<128, 256>>>();
    gemm2_kernel<<<8192, 256, sm2>>>(W2, g1, b1);
    reduce_b<<<128, 256>>>();
    gemm3_kernel<<<16384, 256, sm2>>>(W3, g2, b2);
    reduce_c<<<256, 256>>>();
    final_kernel<<<8192, 256>>>(g3, b3, out + BB * SS * 3);
}